// round 15
// baseline (speedup 1.0000x reference)
#include <cuda_runtime.h>
#include <cuda_bf16.h>
#include <math.h>
#include <stdint.h>

#define B_    16
#define V_    128
#define T_    32
#define DIN_  64
#define HD_   128
#define HN_   32
#define DOUT_ 64
#define NTB   (T_*B_)      /* 512  */
#define NTBV  (NTB*V_)     /* 65536 */
#define WS    136          /* smem row stride in bf16 elements */
#define XS    72           /* k1 smem row stride */
#define K2GRID 148
#define K3GRID 148

// ---------------- scratch ----------------------------------------------------------------
__device__ float          g_ai  [NTBV*HD_];
__device__ __nv_bfloat16  g_bjh [NTBV*HD_];
__device__ __nv_bfloat16  g_aggh[NTBV*HD_];
__device__ float g_m  [NTB*HD_];
__device__ float g_gi [NTB*3*HD_];
__device__ float g_Wpa[DIN_*HD_];
__device__ float g_Wpb[DIN_*HD_];
__device__ float g_ba [HD_];
__device__ float g_bb [HD_];
__device__ int   g_idx [B_*V_*V_];
__device__ float g_adjw[B_*V_*V_];
__device__ int   g_nj  [B_*V_];
__device__ __nv_bfloat16 g_W64h[256*DIN_];
__device__ __nv_bfloat16 g_W64l[256*DIN_];

// ---------------- helpers -----------------------------------------------------------------
__device__ __forceinline__ uint32_t smem_u32(const void* p) {
    uint32_t a;
    asm("{ .reg .u64 t; cvta.to.shared.u64 t, %1; cvt.u32.u64 %0, t; }" : "=r"(a) : "l"(p));
    return a;
}
__device__ __forceinline__ void ldmat_x4(uint32_t& a0, uint32_t& a1, uint32_t& a2, uint32_t& a3, uint32_t addr) {
    asm volatile("ldmatrix.sync.aligned.m8n8.x4.shared.b16 {%0,%1,%2,%3}, [%4];"
        : "=r"(a0), "=r"(a1), "=r"(a2), "=r"(a3) : "r"(addr));
}
__device__ __forceinline__ void mma_bf16(float* c, uint32_t a0, uint32_t a1, uint32_t a2, uint32_t a3,
                                         uint32_t b0, uint32_t b1) {
    asm volatile("mma.sync.aligned.m16n8k16.row.col.f32.bf16.bf16.f32 "
        "{%0,%1,%2,%3}, {%4,%5,%6,%7}, {%8,%9}, {%0,%1,%2,%3};"
        : "+f"(c[0]), "+f"(c[1]), "+f"(c[2]), "+f"(c[3])
        : "r"(a0), "r"(a1), "r"(a2), "r"(a3), "r"(b0), "r"(b1));
}
__device__ __forceinline__ uint32_t pack_hi(float w0, float w1) {
    __nv_bfloat162 p = __float22bfloat162_rn(make_float2(w0, w1));
    return *(uint32_t*)&p;
}
__device__ __forceinline__ uint32_t pack_lo(float w0, float w1) {
    __nv_bfloat16 h0 = __float2bfloat16(w0), h1 = __float2bfloat16(w1);
    float l0 = w0 - __bfloat162float(h0), l1 = w1 - __bfloat162float(h1);
    __nv_bfloat162 p = __float22bfloat162_rn(make_float2(l0, l1));
    return *(uint32_t*)&p;
}

// ---------------- K0: fold x@Wp+bp through W1a/W1b ---------------------------------------
__global__ void k0_prep(const float* __restrict__ Wp, const float* __restrict__ bp,
                        const float* __restrict__ W1, const float* __restrict__ b1) {
    int r = blockIdx.x;
    int which = threadIdx.x >> 7;
    int h = threadIdx.x & 127;
    if (r < DIN_) {
        float acc = 0.f;
        for (int c = 0; c < HD_; ++c)
            acc = fmaf(Wp[r*HD_ + c], W1[(which*HD_ + c)*HD_ + h], acc);
        (which ? g_Wpb : g_Wpa)[r*HD_ + h] = acc;
    } else {
        float acc = which ? 0.f : b1[h];
        for (int c = 0; c < HD_; ++c)
            acc = fmaf(bp[c], W1[(which*HD_ + c)*HD_ + h], acc);
        (which ? g_bb : g_ba)[h] = acc;
    }
}

// ---------------- K0c: split [Wpa|Wpb] into n-major bf16 hi/lo ----------------------------
__global__ void k0c_w64() {
    int idx = blockIdx.x * 256 + threadIdx.x;
    int n = idx >> 6, k = idx & 63;
    float w = (n < 128) ? g_Wpa[k*HD_ + n] : g_Wpb[k*HD_ + (n-128)];
    __nv_bfloat16 hh = __float2bfloat16(w);
    g_W64h[idx] = hh;
    g_W64l[idx] = __float2bfloat16(w - __bfloat162float(hh));
}

// ---------------- K1b: precompute adj compaction per (b,i) --------------------------------
__global__ void k1b_compact(const float* __restrict__ adj) {
    int key = blockIdx.x * 8 + (threadIdx.x >> 5);
    int lane = threadIdx.x & 31;
    const float* arow = adj + (size_t)key * V_;
    float* adjw = g_adjw + (size_t)key * V_;
    int*   idxv = g_idx  + (size_t)key * V_;
    int off = 0;
    #pragma unroll
    for (int q = 0; q < 4; ++q) {
        int j = q*32 + lane;
        float v = arow[j];
        unsigned m = __ballot_sync(0xffffffffu, v != 0.f);
        if (v != 0.f) {
            int pos = off + __popc(m & ((1u << lane) - 1u));
            idxv[pos] = j; adjw[pos] = v;
        }
        off += __popc(m);
    }
    for (int p = off + lane; p < V_; p += 32) adjw[p] = 0.f;
    if (lane == 0) g_nj[key] = off;
}

// ---------------- K1: tensor-core ai/bj = x @ [Wpa|Wpb] + bias (3-term split) -------------
__global__ __launch_bounds__(256) void k1_mma(const float* __restrict__ x) {
    extern __shared__ char smraw[];
    __nv_bfloat16* sXh = (__nv_bfloat16*)smraw;        // [128][XS]
    __nv_bfloat16* sXl = sXh + 128*XS;
    __nv_bfloat16* sWh = sXl + 128*XS;                 // [256][XS]
    __nv_bfloat16* sWl = sWh + 256*XS;
    float* sB = (float*)(sWl + 256*XS);                // [256]
    int tb = blockIdx.x, b = tb & 15, t = tb >> 4, tid = threadIdx.x;
    int lane = tid & 31, wid = tid >> 5;
    int wm = wid & 1, wn = wid >> 1;

    for (int idx = tid; idx < 2048; idx += 256) {
        int n = idx >> 3, c0 = (idx & 7)*8;
        *(uint4*)(sWh + n*XS + c0) = ((const uint4*)g_W64h)[idx];
        *(uint4*)(sWl + n*XS + c0) = ((const uint4*)g_W64l)[idx];
    }
    sB[tid] = (tid < 128) ? g_ba[tid] : g_bb[tid - 128];
    for (int idx = tid; idx < 128*16; idx += 256) {
        int i = idx >> 4, d0 = (idx & 15)*4;
        float4 v = *(const float4*)(x + (((size_t)b*V_ + i)*T_ + t)*DIN_ + d0);
        __nv_bfloat16 h0 = __float2bfloat16(v.x), h1 = __float2bfloat16(v.y);
        __nv_bfloat16 h2 = __float2bfloat16(v.z), h3 = __float2bfloat16(v.w);
        sXh[i*XS + d0    ] = h0; sXh[i*XS + d0 + 1] = h1;
        sXh[i*XS + d0 + 2] = h2; sXh[i*XS + d0 + 3] = h3;
        sXl[i*XS + d0    ] = __float2bfloat16(v.x - __bfloat162float(h0));
        sXl[i*XS + d0 + 1] = __float2bfloat16(v.y - __bfloat162float(h1));
        sXl[i*XS + d0 + 2] = __float2bfloat16(v.z - __bfloat162float(h2));
        sXl[i*XS + d0 + 3] = __float2bfloat16(v.w - __bfloat162float(h3));
    }
    __syncthreads();

    uint32_t sXh_b = smem_u32(sXh), sXl_b = smem_u32(sXl);
    uint32_t sWh_b = smem_u32(sWh), sWl_b = smem_u32(sWl);
    float* outa = g_ai + (size_t)tb*V_*HD_;
    __nv_bfloat16* outb = g_bjh + (size_t)tb*V_*HD_;

    #pragma unroll 1
    for (int mt = 0; mt < 4; ++mt) {
        int m0 = (wm + 2*mt)*16;
        uint32_t arow = (uint32_t)(((m0 + (lane & 15))*XS + (lane >> 4)*8) * 2);
        uint32_t Ah[4][4], Al[4][4];
        #pragma unroll
        for (int ks = 0; ks < 4; ++ks) {
            ldmat_x4(Ah[ks][0], Ah[ks][1], Ah[ks][2], Ah[ks][3], sXh_b + arow + ks*32);
            ldmat_x4(Al[ks][0], Al[ks][1], Al[ks][2], Al[ks][3], sXl_b + arow + ks*32);
        }
        float acc[8][4];
        #pragma unroll
        for (int nt = 0; nt < 8; ++nt)
            #pragma unroll
            for (int e = 0; e < 4; ++e) acc[nt][e] = 0.f;
        #pragma unroll
        for (int ntp = 0; ntp < 4; ++ntp) {
            uint32_t brow = (uint32_t)(((wn*64 + ntp*16 + (lane & 15))*XS + (lane >> 4)*8) * 2);
            #pragma unroll
            for (int ks = 0; ks < 4; ++ks) {
                uint32_t bh[4], bl[4];
                ldmat_x4(bh[0], bh[1], bh[2], bh[3], sWh_b + brow + ks*32);
                ldmat_x4(bl[0], bl[1], bl[2], bl[3], sWl_b + brow + ks*32);
                mma_bf16(acc[2*ntp],   Ah[ks][0], Ah[ks][1], Ah[ks][2], Ah[ks][3], bh[0], bh[2]);
                mma_bf16(acc[2*ntp],   Ah[ks][0], Ah[ks][1], Ah[ks][2], Ah[ks][3], bl[0], bl[2]);
                mma_bf16(acc[2*ntp],   Al[ks][0], Al[ks][1], Al[ks][2], Al[ks][3], bh[0], bh[2]);
                mma_bf16(acc[2*ntp+1], Ah[ks][0], Ah[ks][1], Ah[ks][2], Ah[ks][3], bh[1], bh[3]);
                mma_bf16(acc[2*ntp+1], Ah[ks][0], Ah[ks][1], Ah[ks][2], Ah[ks][3], bl[1], bl[3]);
                mma_bf16(acc[2*ntp+1], Al[ks][0], Al[ks][1], Al[ks][2], Al[ks][3], bh[1], bh[3]);
            }
        }
        int r = m0 + (lane >> 2);
        #pragma unroll
        for (int nt = 0; nt < 8; ++nt) {
            int c = wn*64 + nt*8 + (lane & 3)*2;
            float v0 = acc[nt][0] + sB[c];
            float v1 = acc[nt][1] + sB[c+1];
            float v2 = acc[nt][2] + sB[c];
            float v3 = acc[nt][3] + sB[c+1];
            if (c < 128) {
                *(float2*)(outa + (size_t)r*HD_ + c)     = make_float2(v0, v1);
                *(float2*)(outa + (size_t)(r+8)*HD_ + c) = make_float2(v2, v3);
            } else {
                int cc = c - 128;
                __nv_bfloat162 p0 = __float22bfloat162_rn(make_float2(v0, v1));
                __nv_bfloat162 p1 = __float22bfloat162_rn(make_float2(v2, v3));
                *(uint32_t*)(outb + (size_t)r*HD_ + cc)     = *(uint32_t*)&p0;
                *(uint32_t*)(outb + (size_t)(r+8)*HD_ + cc) = *(uint32_t*)&p1;
            }
        }
    }
}

// ---------------- K2: warp-specialized MMA edge MLP (frozen champion) ---------------------
template<int NT>
__device__ __forceinline__ void k2_build(int n, int tid, const int* __restrict__ idxv,
                                         const float* __restrict__ aiv, int nj,
                                         __nv_bfloat16* __restrict__ sEd) {
    int tb = n >> 7;
    const __nv_bfloat16* bjb = g_bjh + (size_t)tb * V_ * HD_;
    #pragma unroll
    for (int q = 0; q < 2048/NT; ++q) {
        int cid = tid + q*NT;
        int r = cid >> 4, c0 = (cid & 15)*8;
        if (r < nj) {
            int j = idxv[r];
            uint4 u = *(const uint4*)(bjb + (size_t)j*HD_ + c0);
            float2 f0 = __bfloat1622float2(*(__nv_bfloat162*)&u.x);
            float2 f1 = __bfloat1622float2(*(__nv_bfloat162*)&u.y);
            float2 f2 = __bfloat1622float2(*(__nv_bfloat162*)&u.z);
            float2 f3 = __bfloat1622float2(*(__nv_bfloat162*)&u.w);
            f0.x = fmaxf(f0.x + aiv[c0+0], 0.f); f0.y = fmaxf(f0.y + aiv[c0+1], 0.f);
            f1.x = fmaxf(f1.x + aiv[c0+2], 0.f); f1.y = fmaxf(f1.y + aiv[c0+3], 0.f);
            f2.x = fmaxf(f2.x + aiv[c0+4], 0.f); f2.y = fmaxf(f2.y + aiv[c0+5], 0.f);
            f3.x = fmaxf(f3.x + aiv[c0+6], 0.f); f3.y = fmaxf(f3.y + aiv[c0+7], 0.f);
            __nv_bfloat162 o0 = __float22bfloat162_rn(f0);
            __nv_bfloat162 o1 = __float22bfloat162_rn(f1);
            __nv_bfloat162 o2 = __float22bfloat162_rn(f2);
            __nv_bfloat162 o3 = __float22bfloat162_rn(f3);
            uint4 ov;
            ov.x = *(uint32_t*)&o0; ov.y = *(uint32_t*)&o1;
            ov.z = *(uint32_t*)&o2; ov.w = *(uint32_t*)&o3;
            *(uint4*)(sEd + r*WS + c0) = ov;
        }
    }
}

#define K2_OFF_E1   0
#define K2_OFF_AI   69632
#define K2_OFF_ADJW 70656
#define K2_OFF_RED  71680
#define K2_OFF_B2   72704
#define K2_OFF_IDX  73216
#define K2_OFF_NJ   74240
#define K2_SMEM     74304

__global__ __launch_bounds__(512, 1) void k2_edge_mma(const float* __restrict__ W2,
                                                      const float* __restrict__ b2) {
    extern __shared__ char smraw[];
    __nv_bfloat16* sE = (__nv_bfloat16*)(smraw + K2_OFF_E1);   // [2][128*WS]
    float* s_ai   = (float*)(smraw + K2_OFF_AI);
    float* s_adjw = (float*)(smraw + K2_OFF_ADJW);
    float* s_red  = (float*)(smraw + K2_OFF_RED);
    float* s_b2v  = (float*)(smraw + K2_OFF_B2);
    int*   s_idx  = (int*)  (smraw + K2_OFF_IDX);
    int*   s_nj   = (int*)  (smraw + K2_OFF_NJ);

    int tid = threadIdx.x, lane = tid & 31, wid = tid >> 5;
    bool consumer = (wid < 8);
    int ht = wid & 7;
    int g = lane >> 2, tig = lane & 3;
    int h0 = ht*16 + g, h1 = h0 + 8;

    uint32_t Ahi[8][4], Alo[8][4];
    if (consumer) {
        #pragma unroll
        for (int ks = 0; ks < 8; ++ks) {
            #pragma unroll
            for (int f = 0; f < 4; ++f) {
                int row = (f & 1) ? h1 : h0;
                int kb  = ks*16 + tig*2 + ((f >> 1) ? 8 : 0);
                float w0 = W2[kb*HD_ + row];
                float w1 = W2[(kb+1)*HD_ + row];
                Ahi[ks][f] = pack_hi(w0, w1);
                Alo[ks][f] = pack_lo(w0, w1);
            }
        }
    }
    if (tid < 128) { s_b2v[tid] = b2[tid]; s_red[tid] = 0.f; s_red[128 + tid] = 0.f; }
    for (int idx = tid; idx < 128*WS; idx += 512) ((uint32_t*)sE)[idx] = 0u;

    int n0 = blockIdx.x;
    int cnt = (NTBV - n0 + K2GRID - 1) / K2GRID;

    {
        int key0 = ((n0 >> 7) & 15)*128 + (n0 & 127);
        if (tid < 128)       s_ai[tid]          = g_ai[(size_t)n0*HD_ + tid];
        else if (tid < 256)  s_idx[tid - 128]   = g_idx[(size_t)key0*V_ + (tid - 128)];
        else if (tid < 384)  s_adjw[tid - 256]  = g_adjw[(size_t)key0*V_ + (tid - 256)];
        if (tid == 384) s_nj[0] = g_nj[key0];
    }
    __syncthreads();
    float bh0 = s_b2v[h0], bh1 = s_b2v[h1];
    k2_build<512>(n0, tid, s_idx, s_ai, s_nj[0], sE);
    __syncthreads();

    uint32_t sE_base = smem_u32(sE);

    for (int i = 0; i < cnt; ++i) {
        int n = n0 + i*K2GRID;
        int s = i & 1;
        if (consumer) {
            int nj = s_nj[s];
            const float* adjw = s_adjw + s*128;
            uint32_t sEb = sE_base + (uint32_t)(s*128*WS*2);
            float p0 = 0.f, p1 = 0.f;
            #pragma unroll
            for (int jp = 0; jp < 4; ++jp) {
                int jb = jp * 32;
                if (jb < nj) {
                    bool s1 = (jb +  8) < nj;
                    bool s2 = (jb + 16) < nj;
                    bool s3 = (jb + 24) < nj;
                    float ch[4][4], cl[4][4];
                    #pragma unroll
                    for (int st = 0; st < 4; ++st)
                        #pragma unroll
                        for (int e = 0; e < 4; ++e) { ch[st][e] = 0.f; cl[st][e] = 0.f; }
                    uint32_t ba0 = sEb + (uint32_t)(((jb      + (lane & 15))*WS + (lane >> 4)*8) * 2);
                    uint32_t ba1 = ba0 + (uint32_t)(16*WS*2);
                    #pragma unroll
                    for (int ks = 0; ks < 8; ++ks) {
                        uint32_t r0, r1, r2, r3, q0, q1, q2, q3;
                        ldmat_x4(r0, r1, r2, r3, ba0 + ks*32);
                        if (s2) ldmat_x4(q0, q1, q2, q3, ba1 + ks*32);
                        mma_bf16(ch[0], Ahi[ks][0], Ahi[ks][1], Ahi[ks][2], Ahi[ks][3], r0, r2);
                        mma_bf16(cl[0], Alo[ks][0], Alo[ks][1], Alo[ks][2], Alo[ks][3], r0, r2);
                        if (s1) {
                            mma_bf16(ch[1], Ahi[ks][0], Ahi[ks][1], Ahi[ks][2], Ahi[ks][3], r1, r3);
                            mma_bf16(cl[1], Alo[ks][0], Alo[ks][1], Alo[ks][2], Alo[ks][3], r1, r3);
                        }
                        if (s2) {
                            mma_bf16(ch[2], Ahi[ks][0], Ahi[ks][1], Ahi[ks][2], Ahi[ks][3], q0, q2);
                            mma_bf16(cl[2], Alo[ks][0], Alo[ks][1], Alo[ks][2], Alo[ks][3], q0, q2);
                        }
                        if (s3) {
                            mma_bf16(ch[3], Ahi[ks][0], Ahi[ks][1], Ahi[ks][2], Ahi[ks][3], q1, q3);
                            mma_bf16(cl[3], Alo[ks][0], Alo[ks][1], Alo[ks][2], Alo[ks][3], q1, q3);
                        }
                    }
                    #pragma unroll
                    for (int st = 0; st < 4; ++st) {
                        if (jb + st*8 < nj) {
                            int j0 = jb + st*8 + tig*2;
                            float w0 = adjw[j0], w1 = adjw[j0+1];
                            p0 += w0*fmaxf(ch[st][0]+cl[st][0]+bh0, 0.f) + w1*fmaxf(ch[st][1]+cl[st][1]+bh0, 0.f);
                            p1 += w0*fmaxf(ch[st][2]+cl[st][2]+bh1, 0.f) + w1*fmaxf(ch[st][3]+cl[st][3]+bh1, 0.f);
                        }
                    }
                }
            }
            p0 += __shfl_xor_sync(0xffffffffu, p0, 1);
            p0 += __shfl_xor_sync(0xffffffffu, p0, 2);
            p1 += __shfl_xor_sync(0xffffffffu, p1, 1);
            p1 += __shfl_xor_sync(0xffffffffu, p1, 2);
            if (tig == 0) {
                atomicAdd(&s_red[s*128 + h0], p0);
                atomicAdd(&s_red[s*128 + h1], p1);
            }
        } else {
            int ptid = tid - 256;
            int np = n + K2GRID;
            if (ptid < 128) {
                if (i > 0)
                    g_aggh[(size_t)(n - K2GRID)*HD_ + ptid] = __float2bfloat16(s_red[(s^1)*128 + ptid]);
                s_red[(s^1)*128 + ptid] = 0.f;
                if (np < NTBV) s_ai[(s^1)*128 + ptid] = g_ai[(size_t)np*HD_ + ptid];
            } else if (np < NTBV) {
                int r = ptid - 128;
                int keyp = ((np >> 7) & 15)*128 + (np & 127);
                s_idx[(s^1)*128 + r]  = g_idx[(size_t)keyp*V_ + r];
                s_adjw[(s^1)*128 + r] = g_adjw[(size_t)keyp*V_ + r];
                if (r == 0) s_nj[s^1] = g_nj[keyp];
            }
            asm volatile("bar.sync 7, 256;" ::: "memory");
            if (np < NTBV)
                k2_build<256>(np, ptid, s_idx + (s^1)*128, s_ai + (s^1)*128, s_nj[s^1], sE + (s^1)*128*WS);
        }
        __syncthreads();
    }
    int nlast = n0 + (cnt - 1)*K2GRID;
    int sl = (cnt - 1) & 1;
    if (tid < 128) g_aggh[(size_t)nlast*HD_ + tid] = __float2bfloat16(s_red[sl*128 + tid]);
}

// ---------------- K3: warp-MMA node MLP (2 layers, split weights) + mean ------------------
__global__ __launch_bounds__(512, 1) void k3_node_mma(const float* __restrict__ Wn1, const float* __restrict__ bn1,
                                                      const float* __restrict__ Wn2, const float* __restrict__ bn2) {
    extern __shared__ char smraw[];
    __nv_bfloat16* sA   = (__nv_bfloat16*)smraw;
    __nv_bfloat16* sT   = sA + 128*WS;
    __nv_bfloat16* sW1h = sT + 128*WS;
    __nv_bfloat16* sW1l = sW1h + 128*WS;
    __nv_bfloat16* sW2h = sW1l + 128*WS;
    __nv_bfloat16* sW2l = sW2h + 128*WS;
    float* s_red = (float*)(sW2l + 128*WS);
    float* s_b1  = s_red + 128;
    float* s_b2  = s_b1 + 128;

    int tid = threadIdx.x, lane = tid & 31, wid = tid >> 5;
    int wm = wid & 3, wn = wid >> 2;
    int g = lane >> 2, tig = lane & 3;

    for (int idx = tid; idx < HD_*HD_; idx += 512) {
        int nn = idx >> 7, k = idx & 127;
        float w1 = Wn1[k*HD_ + nn];
        float w2 = Wn2[k*HD_ + nn];
        __nv_bfloat16 h1v = __float2bfloat16(w1), h2v = __float2bfloat16(w2);
        sW1h[nn*WS + k] = h1v;
        sW1l[nn*WS + k] = __float2bfloat16(w1 - __bfloat162float(h1v));
        sW2h[nn*WS + k] = h2v;
        sW2l[nn*WS + k] = __float2bfloat16(w2 - __bfloat162float(h2v));
    }
    if (tid < 128) { s_b1[tid] = bn1[tid]; s_b2[tid] = bn2[tid]; }
    __syncthreads();

    uint32_t sA_base  = smem_u32(sA);
    uint32_t sT_base  = smem_u32(sT);
    uint32_t sW1h_b = smem_u32(sW1h), sW1l_b = smem_u32(sW1l);
    uint32_t sW2h_b = smem_u32(sW2h), sW2l_b = smem_u32(sW2l);

    for (int tb = blockIdx.x; tb < NTB; tb += K3GRID) {
        {
            const uint4* src = (const uint4*)(g_aggh + (size_t)tb*V_*HD_);
            #pragma unroll
            for (int q = 0; q < 4; ++q) {
                int cid = tid + q*512;
                int r = cid >> 4, c0 = (cid & 15)*8;
                *(uint4*)(sA + r*WS + c0) = src[cid];
            }
        }
        if (tid < 128) s_red[tid] = 0.f;
        __syncthreads();

        {
            float c[2][4][4];
            #pragma unroll
            for (int m = 0; m < 2; ++m)
                #pragma unroll
                for (int nt = 0; nt < 4; ++nt)
                    #pragma unroll
                    for (int e = 0; e < 4; ++e) c[m][nt][e] = 0.f;
            #pragma unroll
            for (int ks = 0; ks < 8; ++ks) {
                uint32_t koff = (uint32_t)((ks*16 + (lane >> 4)*8) * 2);
                uint32_t rsel = (uint32_t)((lane & 15) * WS * 2);
                uint32_t bh0[4], bh1[4], bl0[4], bl1[4];
                ldmat_x4(bh0[0], bh0[1], bh0[2], bh0[3], sW1h_b + (uint32_t)((wn*32)*WS*2) + rsel + koff);
                ldmat_x4(bh1[0], bh1[1], bh1[2], bh1[3], sW1h_b + (uint32_t)((wn*32+16)*WS*2) + rsel + koff);
                ldmat_x4(bl0[0], bl0[1], bl0[2], bl0[3], sW1l_b + (uint32_t)((wn*32)*WS*2) + rsel + koff);
                ldmat_x4(bl1[0], bl1[1], bl1[2], bl1[3], sW1l_b + (uint32_t)((wn*32+16)*WS*2) + rsel + koff);
                #pragma unroll
                for (int m = 0; m < 2; ++m) {
                    int m0 = (wm + 4*m) * 16;
                    uint32_t a0, a1, a2, a3;
                    ldmat_x4(a0, a1, a2, a3, sA_base + (uint32_t)(((m0 + (lane & 15))*WS)*2) + koff);
                    mma_bf16(c[m][0], a0,a1,a2,a3, bh0[0], bh0[2]);
                    mma_bf16(c[m][0], a0,a1,a2,a3, bl0[0], bl0[2]);
                    mma_bf16(c[m][1], a0,a1,a2,a3, bh0[1], bh0[3]);
                    mma_bf16(c[m][1], a0,a1,a2,a3, bl0[1], bl0[3]);
                    mma_bf16(c[m][2], a0,a1,a2,a3, bh1[0], bh1[2]);
                    mma_bf16(c[m][2], a0,a1,a2,a3, bl1[0], bl1[2]);
                    mma_bf16(c[m][3], a0,a1,a2,a3, bh1[1], bh1[3]);
                    mma_bf16(c[m][3], a0,a1,a2,a3, bl1[1], bl1[3]);
                }
            }
            #pragma unroll
            for (int m = 0; m < 2; ++m) {
                int r = (wm + 4*m)*16 + g;
                #pragma unroll
                for (int nt = 0; nt < 4; ++nt) {
                    int n0 = wn*32 + nt*8 + tig*2;
                    float v0 = fmaxf(c[m][nt][0] + s_b1[n0],   0.f);
                    float v1 = fmaxf(c[m][nt][1] + s_b1[n0+1], 0.f);
                    float v2 = fmaxf(c[m][nt][2] + s_b1[n0],   0.f);
                    float v3 = fmaxf(c[m][nt][3] + s_b1[n0+1], 0.f);
                    *(uint32_t*)((uint16_t*)sT + r*WS + n0)     = pack_hi(v0, v1);
                    *(uint32_t*)((uint16_t*)sT + (r+8)*WS + n0) = pack_hi(v2, v3);
                }
            }
        }
        __syncthreads();

        {
            float c[2][4][4];
            #pragma unroll
            for (int m = 0; m < 2; ++m)
                #pragma unroll
                for (int nt = 0; nt < 4; ++nt)
                    #pragma unroll
                    for (int e = 0; e < 4; ++e) c[m][nt][e] = 0.f;
            #pragma unroll
            for (int ks = 0; ks < 8; ++ks) {
                uint32_t koff = (uint32_t)((ks*16 + (lane >> 4)*8) * 2);
                uint32_t rsel = (uint32_t)((lane & 15) * WS * 2);
                uint32_t bh0[4], bh1[4], bl0[4], bl1[4];
                ldmat_x4(bh0[0], bh0[1], bh0[2], bh0[3], sW2h_b + (uint32_t)((wn*32)*WS*2) + rsel + koff);
                ldmat_x4(bh1[0], bh1[1], bh1[2], bh1[3], sW2h_b + (uint32_t)((wn*32+16)*WS*2) + rsel + koff);
                ldmat_x4(bl0[0], bl0[1], bl0[2], bl0[3], sW2l_b + (uint32_t)((wn*32)*WS*2) + rsel + koff);
                ldmat_x4(bl1[0], bl1[1], bl1[2], bl1[3], sW2l_b + (uint32_t)((wn*32+16)*WS*2) + rsel + koff);
                #pragma unroll
                for (int m = 0; m < 2; ++m) {
                    int m0 = (wm + 4*m) * 16;
                    uint32_t a0, a1, a2, a3;
                    ldmat_x4(a0, a1, a2, a3, sT_base + (uint32_t)(((m0 + (lane & 15))*WS)*2) + koff);
                    mma_bf16(c[m][0], a0,a1,a2,a3, bh0[0], bh0[2]);
                    mma_bf16(c[m][0], a0,a1,a2,a3, bl0[0], bl0[2]);
                    mma_bf16(c[m][1], a0,a1,a2,a3, bh0[1], bh0[3]);
                    mma_bf16(c[m][1], a0,a1,a2,a3, bl0[1], bl0[3]);
                    mma_bf16(c[m][2], a0,a1,a2,a3, bh1[0], bh1[2]);
                    mma_bf16(c[m][2], a0,a1,a2,a3, bl1[0], bl1[2]);
                    mma_bf16(c[m][3], a0,a1,a2,a3, bh1[1], bh1[3]);
                    mma_bf16(c[m][3], a0,a1,a2,a3, bl1[1], bl1[3]);
                }
            }
            #pragma unroll
            for (int nt = 0; nt < 4; ++nt) {
                int n0 = wn*32 + nt*8 + tig*2;
                float bb0 = s_b2[n0], bb1 = s_b2[n0+1];
                float p0 = 0.f, p1 = 0.f;
                #pragma unroll
                for (int m = 0; m < 2; ++m) {
                    p0 += fmaxf(c[m][nt][0]+bb0, 0.f) + fmaxf(c[m][nt][2]+bb0, 0.f);
                    p1 += fmaxf(c[m][nt][1]+bb1, 0.f) + fmaxf(c[m][nt][3]+bb1, 0.f);
                }
                #pragma unroll
                for (int off = 4; off < 32; off <<= 1) {
                    p0 += __shfl_xor_sync(0xffffffffu, p0, off);
                    p1 += __shfl_xor_sync(0xffffffffu, p1, off);
                }
                if (lane < 4) {
                    atomicAdd(&s_red[n0],   p0);
                    atomicAdd(&s_red[n0+1], p1);
                }
            }
        }
        __syncthreads();
        if (tid < 128) g_m[(size_t)tb*HD_ + tid] = s_red[tid] * (1.0f/(float)V_);
        __syncthreads();
    }
}

// ---------------- K4a: cumsum over t ------------------------------------------------------
__global__ void k4a_cumsum() {
    int gid = blockIdx.x * 1024 + threadIdx.x;
    int b = gid >> 7, h = gid & 127;
    float run = 0.f;
    for (int t = 0; t < T_; ++t) {
        size_t idx = ((size_t)t*B_ + b)*HD_ + h;
        run += g_m[idx];
        g_m[idx] = run;
    }
}

// ---------------- K4b: gi = cum @ Wih^T + bih ---------------------------------------------
__global__ __launch_bounds__(384) void k4b_gi(const float* __restrict__ Wih, const float* __restrict__ bih) {
    __shared__ float s_c[128];
    int tb = blockIdx.x, tid = threadIdx.x;
    if (tid < 128) s_c[tid] = g_m[(size_t)tb*HD_ + tid];
    __syncthreads();
    float a0 = bih[tid], a1 = 0.f, a2 = 0.f, a3 = 0.f;
    const float* wr = Wih + (size_t)tid*HD_;
    #pragma unroll 8
    for (int k = 0; k < HD_; k += 4) {
        a0 = fmaf(s_c[k  ], wr[k  ], a0);
        a1 = fmaf(s_c[k+1], wr[k+1], a1);
        a2 = fmaf(s_c[k+2], wr[k+2], a2);
        a3 = fmaf(s_c[k+3], wr[k+3], a3);
    }
    g_gi[(size_t)tb*3*HD_ + tid] = (a0+a1)+(a2+a3);
}

// ---------------- K5: GRU (batch 16) + fused output projection + HN broadcast -------------
__global__ __launch_bounds__(384) void k5_gru(const float* __restrict__ Whh, const float* __restrict__ bhh,
                                              const float* __restrict__ Wo,  const float* __restrict__ bo,
                                              float* __restrict__ out) {
    extern __shared__ float sm[];
    float* s_W  = sm;                 // [384][129]
    float* s_h  = sm + 384*129;       // [128]
    float* s_gh = s_h + 128;          // [384]
    float* s_o  = s_gh + 384;         // [64]
    int b = blockIdx.x, tid = threadIdx.x;
    for (int idx = tid; idx < 384*HD_; idx += 384) {
        int g = idx >> 7, k = idx & 127;
        s_W[g*129 + k] = Whh[idx];
    }
    float bh = bhh[tid];
    if (tid < 128) s_h[tid] = 0.f;
    __syncthreads();
    const float* wr = s_W + tid*129;
    for (int t = 0; t < T_; ++t) {
        float a0 = bh, a1 = 0.f, a2 = 0.f, a3 = 0.f;
        #pragma unroll 8
        for (int k = 0; k < HD_; k += 4) {
            a0 = fmaf(s_h[k  ], wr[k  ], a0);
            a1 = fmaf(s_h[k+1], wr[k+1], a1);
            a2 = fmaf(s_h[k+2], wr[k+2], a2);
            a3 = fmaf(s_h[k+3], wr[k+3], a3);
        }
        s_gh[tid] = (a0+a1)+(a2+a3);
        __syncthreads();
        if (tid < 128) {
            size_t row = ((size_t)t*B_ + b)*3*HD_;
            float r  = 1.f/(1.f + expf(-(g_gi[row +        tid] + s_gh[tid])));
            float z  = 1.f/(1.f + expf(-(g_gi[row + HD_ +  tid] + s_gh[HD_ + tid])));
            float nn = tanhf(g_gi[row + 2*HD_ + tid] + r*s_gh[2*HD_ + tid]);
            float hp = s_h[tid];
            s_h[tid] = (1.f - z)*nn + z*hp;
        }
        __syncthreads();
        // fused projection: s_o = s_h @ Wo + bo (Wo L1-resident across t)
        if (tid < DOUT_) {
            float c0 = bo[tid], c1 = 0.f, c2 = 0.f, c3 = 0.f;
            #pragma unroll 8
            for (int k = 0; k < HD_; k += 4) {
                c0 = fmaf(s_h[k  ], Wo[(k  )*DOUT_ + tid], c0);
                c1 = fmaf(s_h[k+1], Wo[(k+1)*DOUT_ + tid], c1);
                c2 = fmaf(s_h[k+2], Wo[(k+2)*DOUT_ + tid], c2);
                c3 = fmaf(s_h[k+3], Wo[(k+3)*DOUT_ + tid], c3);
            }
            s_o[tid] = (c0+c1)+(c2+c3);
        }
        __syncthreads();
        for (int idx = tid; idx < HN_*DOUT_; idx += 384) {
            int hn = idx >> 6, d = idx & 63;
            out[(((size_t)b*HN_ + hn)*T_ + t)*DOUT_ + d] = s_o[d];
        }
        // next iteration's s_gh compute reads only s_h (stable); s_o rewritten
        // only after the __syncthreads following the gate update.
    }
}

// ---------------- launch ------------------------------------------------------------------
extern "C" void kernel_launch(void* const* d_in, const int* in_sizes, int n_in,
                              void* d_out, int out_size) {
    const float* x   = (const float*)d_in[0];
    const float* adj = (const float*)d_in[1];
    const float* Wp  = (const float*)d_in[2];
    const float* bp  = (const float*)d_in[3];
    const float* W1  = (const float*)d_in[4];
    const float* b1  = (const float*)d_in[5];
    const float* W2  = (const float*)d_in[6];
    const float* b2  = (const float*)d_in[7];
    const float* Wn1 = (const float*)d_in[8];
    const float* bn1 = (const float*)d_in[9];
    const float* Wn2 = (const float*)d_in[10];
    const float* bn2 = (const float*)d_in[11];
    const float* Wih = (const float*)d_in[12];
    const float* Whh = (const float*)d_in[13];
    const float* bih = (const float*)d_in[14];
    const float* bhh = (const float*)d_in[15];
    const float* Wo  = (const float*)d_in[16];
    const float* bo  = (const float*)d_in[17];
    float* out = (float*)d_out;

    size_t smem1 = (size_t)(2*128*XS*2 + 2*256*XS*2 + 256*4);     // 111,616 B
    size_t smem2 = (size_t)K2_SMEM;                               // 74,304 B
    size_t smem3 = (size_t)(6 * 128 * WS * 2 + (128*3) * 4);      // 210,432 B
    size_t smem5 = (size_t)(384*129 + 128 + 384 + 64) * sizeof(float);

    cudaFuncSetAttribute(k1_mma,      cudaFuncAttributeMaxDynamicSharedMemorySize, (int)smem1);
    cudaFuncSetAttribute(k2_edge_mma, cudaFuncAttributeMaxDynamicSharedMemorySize, (int)smem2);
    cudaFuncSetAttribute(k3_node_mma, cudaFuncAttributeMaxDynamicSharedMemorySize, (int)smem3);
    cudaFuncSetAttribute(k5_gru,      cudaFuncAttributeMaxDynamicSharedMemorySize, (int)smem5);

    k0_prep    <<<DIN_ + 1, 256>>>(Wp, bp, W1, b1);
    k0c_w64    <<<64, 256>>>();
    k1b_compact<<<256, 256>>>(adj);
    k1_mma     <<<NTB, 256, smem1>>>(x);
    k2_edge_mma<<<K2GRID, 512, smem2>>>(W2, b2);
    k3_node_mma<<<K3GRID, 512, smem3>>>(Wn1, bn1, Wn2, bn2);
    k4a_cumsum <<<2, 1024>>>();
    k4b_gi     <<<NTB, 384>>>(Wih, bih);
    k5_gru     <<<B_, 384, smem5>>>(Whh, bhh, Wo, bo, out);
}

// round 16
// speedup vs baseline: 1.1512x; 1.1512x over previous
#include <cuda_runtime.h>
#include <cuda_bf16.h>
#include <math.h>
#include <stdint.h>

#define B_    16
#define V_    128
#define T_    32
#define DIN_  64
#define HD_   128
#define HN_   32
#define DOUT_ 64
#define NTB   (T_*B_)      /* 512  */
#define NTBV  (NTB*V_)     /* 65536 */
#define WS    136          /* smem row stride in bf16 elements */
#define XS    72           /* k1 smem row stride */
#define K2GRID 148
#define K3GRID 148

// ---------------- scratch ----------------------------------------------------------------
__device__ float          g_ai  [NTBV*HD_];
__device__ __nv_bfloat16  g_bjh [NTBV*HD_];
__device__ __nv_bfloat16  g_aggh[NTBV*HD_];
__device__ float g_m  [NTB*HD_];
__device__ float g_gi [NTB*3*HD_];
__device__ float g_y  [NTB*HD_];
__device__ float g_Wpa[DIN_*HD_];
__device__ float g_Wpb[DIN_*HD_];
__device__ float g_ba [HD_];
__device__ float g_bb [HD_];
__device__ int   g_idx [B_*V_*V_];
__device__ float g_adjw[B_*V_*V_];
__device__ int   g_nj  [B_*V_];
__device__ __nv_bfloat16 g_W64h[256*DIN_];
__device__ __nv_bfloat16 g_W64l[256*DIN_];

// ---------------- helpers -----------------------------------------------------------------
__device__ __forceinline__ uint32_t smem_u32(const void* p) {
    uint32_t a;
    asm("{ .reg .u64 t; cvta.to.shared.u64 t, %1; cvt.u32.u64 %0, t; }" : "=r"(a) : "l"(p));
    return a;
}
__device__ __forceinline__ void ldmat_x4(uint32_t& a0, uint32_t& a1, uint32_t& a2, uint32_t& a3, uint32_t addr) {
    asm volatile("ldmatrix.sync.aligned.m8n8.x4.shared.b16 {%0,%1,%2,%3}, [%4];"
        : "=r"(a0), "=r"(a1), "=r"(a2), "=r"(a3) : "r"(addr));
}
__device__ __forceinline__ void mma_bf16(float* c, uint32_t a0, uint32_t a1, uint32_t a2, uint32_t a3,
                                         uint32_t b0, uint32_t b1) {
    asm volatile("mma.sync.aligned.m16n8k16.row.col.f32.bf16.bf16.f32 "
        "{%0,%1,%2,%3}, {%4,%5,%6,%7}, {%8,%9}, {%0,%1,%2,%3};"
        : "+f"(c[0]), "+f"(c[1]), "+f"(c[2]), "+f"(c[3])
        : "r"(a0), "r"(a1), "r"(a2), "r"(a3), "r"(b0), "r"(b1));
}
__device__ __forceinline__ uint32_t pack_hi(float w0, float w1) {
    __nv_bfloat162 p = __float22bfloat162_rn(make_float2(w0, w1));
    return *(uint32_t*)&p;
}
__device__ __forceinline__ uint32_t pack_lo(float w0, float w1) {
    __nv_bfloat16 h0 = __float2bfloat16(w0), h1 = __float2bfloat16(w1);
    float l0 = w0 - __bfloat162float(h0), l1 = w1 - __bfloat162float(h1);
    __nv_bfloat162 p = __float22bfloat162_rn(make_float2(l0, l1));
    return *(uint32_t*)&p;
}

// ---------------- K0: fold x@Wp+bp through W1a/W1b ---------------------------------------
__global__ void k0_prep(const float* __restrict__ Wp, const float* __restrict__ bp,
                        const float* __restrict__ W1, const float* __restrict__ b1) {
    int r = blockIdx.x;
    int which = threadIdx.x >> 7;
    int h = threadIdx.x & 127;
    if (r < DIN_) {
        float acc = 0.f;
        for (int c = 0; c < HD_; ++c)
            acc = fmaf(Wp[r*HD_ + c], W1[(which*HD_ + c)*HD_ + h], acc);
        (which ? g_Wpb : g_Wpa)[r*HD_ + h] = acc;
    } else {
        float acc = which ? 0.f : b1[h];
        for (int c = 0; c < HD_; ++c)
            acc = fmaf(bp[c], W1[(which*HD_ + c)*HD_ + h], acc);
        (which ? g_bb : g_ba)[h] = acc;
    }
}

// ---------------- K0c: split [Wpa|Wpb] into n-major bf16 hi/lo ----------------------------
__global__ void k0c_w64() {
    int idx = blockIdx.x * 256 + threadIdx.x;
    int n = idx >> 6, k = idx & 63;
    float w = (n < 128) ? g_Wpa[k*HD_ + n] : g_Wpb[k*HD_ + (n-128)];
    __nv_bfloat16 hh = __float2bfloat16(w);
    g_W64h[idx] = hh;
    g_W64l[idx] = __float2bfloat16(w - __bfloat162float(hh));
}

// ---------------- K1b: precompute adj compaction per (b,i) --------------------------------
__global__ void k1b_compact(const float* __restrict__ adj) {
    int key = blockIdx.x * 8 + (threadIdx.x >> 5);
    int lane = threadIdx.x & 31;
    const float* arow = adj + (size_t)key * V_;
    float* adjw = g_adjw + (size_t)key * V_;
    int*   idxv = g_idx  + (size_t)key * V_;
    int off = 0;
    #pragma unroll
    for (int q = 0; q < 4; ++q) {
        int j = q*32 + lane;
        float v = arow[j];
        unsigned m = __ballot_sync(0xffffffffu, v != 0.f);
        if (v != 0.f) {
            int pos = off + __popc(m & ((1u << lane) - 1u));
            idxv[pos] = j; adjw[pos] = v;
        }
        off += __popc(m);
    }
    for (int p = off + lane; p < V_; p += 32) adjw[p] = 0.f;
    if (lane == 0) g_nj[key] = off;
}

// ---------------- K1: tensor-core ai/bj = x @ [Wpa|Wpb] + bias (3-term split) -------------
__global__ __launch_bounds__(256) void k1_mma(const float* __restrict__ x) {
    extern __shared__ char smraw[];
    __nv_bfloat16* sXh = (__nv_bfloat16*)smraw;        // [128][XS]
    __nv_bfloat16* sXl = sXh + 128*XS;
    __nv_bfloat16* sWh = sXl + 128*XS;                 // [256][XS]
    __nv_bfloat16* sWl = sWh + 256*XS;
    float* sB = (float*)(sWl + 256*XS);                // [256]
    int tb = blockIdx.x, b = tb & 15, t = tb >> 4, tid = threadIdx.x;
    int lane = tid & 31, wid = tid >> 5;
    int wm = wid & 1, wn = wid >> 1;

    for (int idx = tid; idx < 2048; idx += 256) {
        int n = idx >> 3, c0 = (idx & 7)*8;
        *(uint4*)(sWh + n*XS + c0) = ((const uint4*)g_W64h)[idx];
        *(uint4*)(sWl + n*XS + c0) = ((const uint4*)g_W64l)[idx];
    }
    sB[tid] = (tid < 128) ? g_ba[tid] : g_bb[tid - 128];
    for (int idx = tid; idx < 128*16; idx += 256) {
        int i = idx >> 4, d0 = (idx & 15)*4;
        float4 v = *(const float4*)(x + (((size_t)b*V_ + i)*T_ + t)*DIN_ + d0);
        __nv_bfloat16 h0 = __float2bfloat16(v.x), h1 = __float2bfloat16(v.y);
        __nv_bfloat16 h2 = __float2bfloat16(v.z), h3 = __float2bfloat16(v.w);
        sXh[i*XS + d0    ] = h0; sXh[i*XS + d0 + 1] = h1;
        sXh[i*XS + d0 + 2] = h2; sXh[i*XS + d0 + 3] = h3;
        sXl[i*XS + d0    ] = __float2bfloat16(v.x - __bfloat162float(h0));
        sXl[i*XS + d0 + 1] = __float2bfloat16(v.y - __bfloat162float(h1));
        sXl[i*XS + d0 + 2] = __float2bfloat16(v.z - __bfloat162float(h2));
        sXl[i*XS + d0 + 3] = __float2bfloat16(v.w - __bfloat162float(h3));
    }
    __syncthreads();

    uint32_t sXh_b = smem_u32(sXh), sXl_b = smem_u32(sXl);
    uint32_t sWh_b = smem_u32(sWh), sWl_b = smem_u32(sWl);
    float* outa = g_ai + (size_t)tb*V_*HD_;
    __nv_bfloat16* outb = g_bjh + (size_t)tb*V_*HD_;

    #pragma unroll 1
    for (int mt = 0; mt < 4; ++mt) {
        int m0 = (wm + 2*mt)*16;
        uint32_t arow = (uint32_t)(((m0 + (lane & 15))*XS + (lane >> 4)*8) * 2);
        uint32_t Ah[4][4], Al[4][4];
        #pragma unroll
        for (int ks = 0; ks < 4; ++ks) {
            ldmat_x4(Ah[ks][0], Ah[ks][1], Ah[ks][2], Ah[ks][3], sXh_b + arow + ks*32);
            ldmat_x4(Al[ks][0], Al[ks][1], Al[ks][2], Al[ks][3], sXl_b + arow + ks*32);
        }
        float acc[8][4];
        #pragma unroll
        for (int nt = 0; nt < 8; ++nt)
            #pragma unroll
            for (int e = 0; e < 4; ++e) acc[nt][e] = 0.f;
        #pragma unroll
        for (int ntp = 0; ntp < 4; ++ntp) {
            uint32_t brow = (uint32_t)(((wn*64 + ntp*16 + (lane & 15))*XS + (lane >> 4)*8) * 2);
            #pragma unroll
            for (int ks = 0; ks < 4; ++ks) {
                uint32_t bh[4], bl[4];
                ldmat_x4(bh[0], bh[1], bh[2], bh[3], sWh_b + brow + ks*32);
                ldmat_x4(bl[0], bl[1], bl[2], bl[3], sWl_b + brow + ks*32);
                mma_bf16(acc[2*ntp],   Ah[ks][0], Ah[ks][1], Ah[ks][2], Ah[ks][3], bh[0], bh[2]);
                mma_bf16(acc[2*ntp],   Ah[ks][0], Ah[ks][1], Ah[ks][2], Ah[ks][3], bl[0], bl[2]);
                mma_bf16(acc[2*ntp],   Al[ks][0], Al[ks][1], Al[ks][2], Al[ks][3], bh[0], bh[2]);
                mma_bf16(acc[2*ntp+1], Ah[ks][0], Ah[ks][1], Ah[ks][2], Ah[ks][3], bh[1], bh[3]);
                mma_bf16(acc[2*ntp+1], Ah[ks][0], Ah[ks][1], Ah[ks][2], Ah[ks][3], bl[1], bl[3]);
                mma_bf16(acc[2*ntp+1], Al[ks][0], Al[ks][1], Al[ks][2], Al[ks][3], bh[1], bh[3]);
            }
        }
        int r = m0 + (lane >> 2);
        #pragma unroll
        for (int nt = 0; nt < 8; ++nt) {
            int c = wn*64 + nt*8 + (lane & 3)*2;
            float v0 = acc[nt][0] + sB[c];
            float v1 = acc[nt][1] + sB[c+1];
            float v2 = acc[nt][2] + sB[c];
            float v3 = acc[nt][3] + sB[c+1];
            if (c < 128) {
                *(float2*)(outa + (size_t)r*HD_ + c)     = make_float2(v0, v1);
                *(float2*)(outa + (size_t)(r+8)*HD_ + c) = make_float2(v2, v3);
            } else {
                int cc = c - 128;
                __nv_bfloat162 p0 = __float22bfloat162_rn(make_float2(v0, v1));
                __nv_bfloat162 p1 = __float22bfloat162_rn(make_float2(v2, v3));
                *(uint32_t*)(outb + (size_t)r*HD_ + cc)     = *(uint32_t*)&p0;
                *(uint32_t*)(outb + (size_t)(r+8)*HD_ + cc) = *(uint32_t*)&p1;
            }
        }
    }
}

// ---------------- K2: warp-specialized MMA edge MLP (frozen champion) ---------------------
template<int NT>
__device__ __forceinline__ void k2_build(int n, int tid, const int* __restrict__ idxv,
                                         const float* __restrict__ aiv, int nj,
                                         __nv_bfloat16* __restrict__ sEd) {
    int tb = n >> 7;
    const __nv_bfloat16* bjb = g_bjh + (size_t)tb * V_ * HD_;
    #pragma unroll
    for (int q = 0; q < 2048/NT; ++q) {
        int cid = tid + q*NT;
        int r = cid >> 4, c0 = (cid & 15)*8;
        if (r < nj) {
            int j = idxv[r];
            uint4 u = *(const uint4*)(bjb + (size_t)j*HD_ + c0);
            float2 f0 = __bfloat1622float2(*(__nv_bfloat162*)&u.x);
            float2 f1 = __bfloat1622float2(*(__nv_bfloat162*)&u.y);
            float2 f2 = __bfloat1622float2(*(__nv_bfloat162*)&u.z);
            float2 f3 = __bfloat1622float2(*(__nv_bfloat162*)&u.w);
            f0.x = fmaxf(f0.x + aiv[c0+0], 0.f); f0.y = fmaxf(f0.y + aiv[c0+1], 0.f);
            f1.x = fmaxf(f1.x + aiv[c0+2], 0.f); f1.y = fmaxf(f1.y + aiv[c0+3], 0.f);
            f2.x = fmaxf(f2.x + aiv[c0+4], 0.f); f2.y = fmaxf(f2.y + aiv[c0+5], 0.f);
            f3.x = fmaxf(f3.x + aiv[c0+6], 0.f); f3.y = fmaxf(f3.y + aiv[c0+7], 0.f);
            __nv_bfloat162 o0 = __float22bfloat162_rn(f0);
            __nv_bfloat162 o1 = __float22bfloat162_rn(f1);
            __nv_bfloat162 o2 = __float22bfloat162_rn(f2);
            __nv_bfloat162 o3 = __float22bfloat162_rn(f3);
            uint4 ov;
            ov.x = *(uint32_t*)&o0; ov.y = *(uint32_t*)&o1;
            ov.z = *(uint32_t*)&o2; ov.w = *(uint32_t*)&o3;
            *(uint4*)(sEd + r*WS + c0) = ov;
        }
    }
}

#define K2_OFF_E1   0
#define K2_OFF_AI   69632
#define K2_OFF_ADJW 70656
#define K2_OFF_RED  71680
#define K2_OFF_B2   72704
#define K2_OFF_IDX  73216
#define K2_OFF_NJ   74240
#define K2_SMEM     74304

__global__ __launch_bounds__(512, 1) void k2_edge_mma(const float* __restrict__ W2,
                                                      const float* __restrict__ b2) {
    extern __shared__ char smraw[];
    __nv_bfloat16* sE = (__nv_bfloat16*)(smraw + K2_OFF_E1);   // [2][128*WS]
    float* s_ai   = (float*)(smraw + K2_OFF_AI);
    float* s_adjw = (float*)(smraw + K2_OFF_ADJW);
    float* s_red  = (float*)(smraw + K2_OFF_RED);
    float* s_b2v  = (float*)(smraw + K2_OFF_B2);
    int*   s_idx  = (int*)  (smraw + K2_OFF_IDX);
    int*   s_nj   = (int*)  (smraw + K2_OFF_NJ);

    int tid = threadIdx.x, lane = tid & 31, wid = tid >> 5;
    bool consumer = (wid < 8);
    int ht = wid & 7;
    int g = lane >> 2, tig = lane & 3;
    int h0 = ht*16 + g, h1 = h0 + 8;

    uint32_t Ahi[8][4], Alo[8][4];
    if (consumer) {
        #pragma unroll
        for (int ks = 0; ks < 8; ++ks) {
            #pragma unroll
            for (int f = 0; f < 4; ++f) {
                int row = (f & 1) ? h1 : h0;
                int kb  = ks*16 + tig*2 + ((f >> 1) ? 8 : 0);
                float w0 = W2[kb*HD_ + row];
                float w1 = W2[(kb+1)*HD_ + row];
                Ahi[ks][f] = pack_hi(w0, w1);
                Alo[ks][f] = pack_lo(w0, w1);
            }
        }
    }
    if (tid < 128) { s_b2v[tid] = b2[tid]; s_red[tid] = 0.f; s_red[128 + tid] = 0.f; }
    for (int idx = tid; idx < 128*WS; idx += 512) ((uint32_t*)sE)[idx] = 0u;

    int n0 = blockIdx.x;
    int cnt = (NTBV - n0 + K2GRID - 1) / K2GRID;

    {
        int key0 = ((n0 >> 7) & 15)*128 + (n0 & 127);
        if (tid < 128)       s_ai[tid]          = g_ai[(size_t)n0*HD_ + tid];
        else if (tid < 256)  s_idx[tid - 128]   = g_idx[(size_t)key0*V_ + (tid - 128)];
        else if (tid < 384)  s_adjw[tid - 256]  = g_adjw[(size_t)key0*V_ + (tid - 256)];
        if (tid == 384) s_nj[0] = g_nj[key0];
    }
    __syncthreads();
    float bh0 = s_b2v[h0], bh1 = s_b2v[h1];
    k2_build<512>(n0, tid, s_idx, s_ai, s_nj[0], sE);
    __syncthreads();

    uint32_t sE_base = smem_u32(sE);

    for (int i = 0; i < cnt; ++i) {
        int n = n0 + i*K2GRID;
        int s = i & 1;
        if (consumer) {
            int nj = s_nj[s];
            const float* adjw = s_adjw + s*128;
            uint32_t sEb = sE_base + (uint32_t)(s*128*WS*2);
            float p0 = 0.f, p1 = 0.f;
            #pragma unroll
            for (int jp = 0; jp < 4; ++jp) {
                int jb = jp * 32;
                if (jb < nj) {
                    bool s1 = (jb +  8) < nj;
                    bool s2 = (jb + 16) < nj;
                    bool s3 = (jb + 24) < nj;
                    float ch[4][4], cl[4][4];
                    #pragma unroll
                    for (int st = 0; st < 4; ++st)
                        #pragma unroll
                        for (int e = 0; e < 4; ++e) { ch[st][e] = 0.f; cl[st][e] = 0.f; }
                    uint32_t ba0 = sEb + (uint32_t)(((jb      + (lane & 15))*WS + (lane >> 4)*8) * 2);
                    uint32_t ba1 = ba0 + (uint32_t)(16*WS*2);
                    #pragma unroll
                    for (int ks = 0; ks < 8; ++ks) {
                        uint32_t r0, r1, r2, r3, q0, q1, q2, q3;
                        ldmat_x4(r0, r1, r2, r3, ba0 + ks*32);
                        if (s2) ldmat_x4(q0, q1, q2, q3, ba1 + ks*32);
                        mma_bf16(ch[0], Ahi[ks][0], Ahi[ks][1], Ahi[ks][2], Ahi[ks][3], r0, r2);
                        mma_bf16(cl[0], Alo[ks][0], Alo[ks][1], Alo[ks][2], Alo[ks][3], r0, r2);
                        if (s1) {
                            mma_bf16(ch[1], Ahi[ks][0], Ahi[ks][1], Ahi[ks][2], Ahi[ks][3], r1, r3);
                            mma_bf16(cl[1], Alo[ks][0], Alo[ks][1], Alo[ks][2], Alo[ks][3], r1, r3);
                        }
                        if (s2) {
                            mma_bf16(ch[2], Ahi[ks][0], Ahi[ks][1], Ahi[ks][2], Ahi[ks][3], q0, q2);
                            mma_bf16(cl[2], Alo[ks][0], Alo[ks][1], Alo[ks][2], Alo[ks][3], q0, q2);
                        }
                        if (s3) {
                            mma_bf16(ch[3], Ahi[ks][0], Ahi[ks][1], Ahi[ks][2], Ahi[ks][3], q1, q3);
                            mma_bf16(cl[3], Alo[ks][0], Alo[ks][1], Alo[ks][2], Alo[ks][3], q1, q3);
                        }
                    }
                    #pragma unroll
                    for (int st = 0; st < 4; ++st) {
                        if (jb + st*8 < nj) {
                            int j0 = jb + st*8 + tig*2;
                            float w0 = adjw[j0], w1 = adjw[j0+1];
                            p0 += w0*fmaxf(ch[st][0]+cl[st][0]+bh0, 0.f) + w1*fmaxf(ch[st][1]+cl[st][1]+bh0, 0.f);
                            p1 += w0*fmaxf(ch[st][2]+cl[st][2]+bh1, 0.f) + w1*fmaxf(ch[st][3]+cl[st][3]+bh1, 0.f);
                        }
                    }
                }
            }
            p0 += __shfl_xor_sync(0xffffffffu, p0, 1);
            p0 += __shfl_xor_sync(0xffffffffu, p0, 2);
            p1 += __shfl_xor_sync(0xffffffffu, p1, 1);
            p1 += __shfl_xor_sync(0xffffffffu, p1, 2);
            if (tig == 0) {
                atomicAdd(&s_red[s*128 + h0], p0);
                atomicAdd(&s_red[s*128 + h1], p1);
            }
        } else {
            int ptid = tid - 256;
            int np = n + K2GRID;
            if (ptid < 128) {
                if (i > 0)
                    g_aggh[(size_t)(n - K2GRID)*HD_ + ptid] = __float2bfloat16(s_red[(s^1)*128 + ptid]);
                s_red[(s^1)*128 + ptid] = 0.f;
                if (np < NTBV) s_ai[(s^1)*128 + ptid] = g_ai[(size_t)np*HD_ + ptid];
            } else if (np < NTBV) {
                int r = ptid - 128;
                int keyp = ((np >> 7) & 15)*128 + (np & 127);
                s_idx[(s^1)*128 + r]  = g_idx[(size_t)keyp*V_ + r];
                s_adjw[(s^1)*128 + r] = g_adjw[(size_t)keyp*V_ + r];
                if (r == 0) s_nj[s^1] = g_nj[keyp];
            }
            asm volatile("bar.sync 7, 256;" ::: "memory");
            if (np < NTBV)
                k2_build<256>(np, ptid, s_idx + (s^1)*128, s_ai + (s^1)*128, s_nj[s^1], sE + (s^1)*128*WS);
        }
        __syncthreads();
    }
    int nlast = n0 + (cnt - 1)*K2GRID;
    int sl = (cnt - 1) & 1;
    if (tid < 128) g_aggh[(size_t)nlast*HD_ + tid] = __float2bfloat16(s_red[sl*128 + tid]);
}

// ---------------- K3: warp-MMA node MLP (2 layers, split weights) + mean ------------------
__global__ __launch_bounds__(512, 1) void k3_node_mma(const float* __restrict__ Wn1, const float* __restrict__ bn1,
                                                      const float* __restrict__ Wn2, const float* __restrict__ bn2) {
    extern __shared__ char smraw[];
    __nv_bfloat16* sA   = (__nv_bfloat16*)smraw;
    __nv_bfloat16* sT   = sA + 128*WS;
    __nv_bfloat16* sW1h = sT + 128*WS;
    __nv_bfloat16* sW1l = sW1h + 128*WS;
    __nv_bfloat16* sW2h = sW1l + 128*WS;
    __nv_bfloat16* sW2l = sW2h + 128*WS;
    float* s_red = (float*)(sW2l + 128*WS);
    float* s_b1  = s_red + 128;
    float* s_b2  = s_b1 + 128;

    int tid = threadIdx.x, lane = tid & 31, wid = tid >> 5;
    int wm = wid & 3, wn = wid >> 2;
    int g = lane >> 2, tig = lane & 3;

    for (int idx = tid; idx < HD_*HD_; idx += 512) {
        int nn = idx >> 7, k = idx & 127;
        float w1 = Wn1[k*HD_ + nn];
        float w2 = Wn2[k*HD_ + nn];
        __nv_bfloat16 h1v = __float2bfloat16(w1), h2v = __float2bfloat16(w2);
        sW1h[nn*WS + k] = h1v;
        sW1l[nn*WS + k] = __float2bfloat16(w1 - __bfloat162float(h1v));
        sW2h[nn*WS + k] = h2v;
        sW2l[nn*WS + k] = __float2bfloat16(w2 - __bfloat162float(h2v));
    }
    if (tid < 128) { s_b1[tid] = bn1[tid]; s_b2[tid] = bn2[tid]; }
    __syncthreads();

    uint32_t sA_base  = smem_u32(sA);
    uint32_t sT_base  = smem_u32(sT);
    uint32_t sW1h_b = smem_u32(sW1h), sW1l_b = smem_u32(sW1l);
    uint32_t sW2h_b = smem_u32(sW2h), sW2l_b = smem_u32(sW2l);

    for (int tb = blockIdx.x; tb < NTB; tb += K3GRID) {
        {
            const uint4* src = (const uint4*)(g_aggh + (size_t)tb*V_*HD_);
            #pragma unroll
            for (int q = 0; q < 4; ++q) {
                int cid = tid + q*512;
                int r = cid >> 4, c0 = (cid & 15)*8;
                *(uint4*)(sA + r*WS + c0) = src[cid];
            }
        }
        if (tid < 128) s_red[tid] = 0.f;
        __syncthreads();

        {
            float c[2][4][4];
            #pragma unroll
            for (int m = 0; m < 2; ++m)
                #pragma unroll
                for (int nt = 0; nt < 4; ++nt)
                    #pragma unroll
                    for (int e = 0; e < 4; ++e) c[m][nt][e] = 0.f;
            #pragma unroll
            for (int ks = 0; ks < 8; ++ks) {
                uint32_t koff = (uint32_t)((ks*16 + (lane >> 4)*8) * 2);
                uint32_t rsel = (uint32_t)((lane & 15) * WS * 2);
                uint32_t bh0[4], bh1[4], bl0[4], bl1[4];
                ldmat_x4(bh0[0], bh0[1], bh0[2], bh0[3], sW1h_b + (uint32_t)((wn*32)*WS*2) + rsel + koff);
                ldmat_x4(bh1[0], bh1[1], bh1[2], bh1[3], sW1h_b + (uint32_t)((wn*32+16)*WS*2) + rsel + koff);
                ldmat_x4(bl0[0], bl0[1], bl0[2], bl0[3], sW1l_b + (uint32_t)((wn*32)*WS*2) + rsel + koff);
                ldmat_x4(bl1[0], bl1[1], bl1[2], bl1[3], sW1l_b + (uint32_t)((wn*32+16)*WS*2) + rsel + koff);
                #pragma unroll
                for (int m = 0; m < 2; ++m) {
                    int m0 = (wm + 4*m) * 16;
                    uint32_t a0, a1, a2, a3;
                    ldmat_x4(a0, a1, a2, a3, sA_base + (uint32_t)(((m0 + (lane & 15))*WS)*2) + koff);
                    mma_bf16(c[m][0], a0,a1,a2,a3, bh0[0], bh0[2]);
                    mma_bf16(c[m][0], a0,a1,a2,a3, bl0[0], bl0[2]);
                    mma_bf16(c[m][1], a0,a1,a2,a3, bh0[1], bh0[3]);
                    mma_bf16(c[m][1], a0,a1,a2,a3, bl0[1], bl0[3]);
                    mma_bf16(c[m][2], a0,a1,a2,a3, bh1[0], bh1[2]);
                    mma_bf16(c[m][2], a0,a1,a2,a3, bl1[0], bl1[2]);
                    mma_bf16(c[m][3], a0,a1,a2,a3, bh1[1], bh1[3]);
                    mma_bf16(c[m][3], a0,a1,a2,a3, bl1[1], bl1[3]);
                }
            }
            #pragma unroll
            for (int m = 0; m < 2; ++m) {
                int r = (wm + 4*m)*16 + g;
                #pragma unroll
                for (int nt = 0; nt < 4; ++nt) {
                    int n0 = wn*32 + nt*8 + tig*2;
                    float v0 = fmaxf(c[m][nt][0] + s_b1[n0],   0.f);
                    float v1 = fmaxf(c[m][nt][1] + s_b1[n0+1], 0.f);
                    float v2 = fmaxf(c[m][nt][2] + s_b1[n0],   0.f);
                    float v3 = fmaxf(c[m][nt][3] + s_b1[n0+1], 0.f);
                    *(uint32_t*)((uint16_t*)sT + r*WS + n0)     = pack_hi(v0, v1);
                    *(uint32_t*)((uint16_t*)sT + (r+8)*WS + n0) = pack_hi(v2, v3);
                }
            }
        }
        __syncthreads();

        {
            float c[2][4][4];
            #pragma unroll
            for (int m = 0; m < 2; ++m)
                #pragma unroll
                for (int nt = 0; nt < 4; ++nt)
                    #pragma unroll
                    for (int e = 0; e < 4; ++e) c[m][nt][e] = 0.f;
            #pragma unroll
            for (int ks = 0; ks < 8; ++ks) {
                uint32_t koff = (uint32_t)((ks*16 + (lane >> 4)*8) * 2);
                uint32_t rsel = (uint32_t)((lane & 15) * WS * 2);
                uint32_t bh0[4], bh1[4], bl0[4], bl1[4];
                ldmat_x4(bh0[0], bh0[1], bh0[2], bh0[3], sW2h_b + (uint32_t)((wn*32)*WS*2) + rsel + koff);
                ldmat_x4(bh1[0], bh1[1], bh1[2], bh1[3], sW2h_b + (uint32_t)((wn*32+16)*WS*2) + rsel + koff);
                ldmat_x4(bl0[0], bl0[1], bl0[2], bl0[3], sW2l_b + (uint32_t)((wn*32)*WS*2) + rsel + koff);
                ldmat_x4(bl1[0], bl1[1], bl1[2], bl1[3], sW2l_b + (uint32_t)((wn*32+16)*WS*2) + rsel + koff);
                #pragma unroll
                for (int m = 0; m < 2; ++m) {
                    int m0 = (wm + 4*m) * 16;
                    uint32_t a0, a1, a2, a3;
                    ldmat_x4(a0, a1, a2, a3, sT_base + (uint32_t)(((m0 + (lane & 15))*WS)*2) + koff);
                    mma_bf16(c[m][0], a0,a1,a2,a3, bh0[0], bh0[2]);
                    mma_bf16(c[m][0], a0,a1,a2,a3, bl0[0], bl0[2]);
                    mma_bf16(c[m][1], a0,a1,a2,a3, bh0[1], bh0[3]);
                    mma_bf16(c[m][1], a0,a1,a2,a3, bl0[1], bl0[3]);
                    mma_bf16(c[m][2], a0,a1,a2,a3, bh1[0], bh1[2]);
                    mma_bf16(c[m][2], a0,a1,a2,a3, bl1[0], bl1[2]);
                    mma_bf16(c[m][3], a0,a1,a2,a3, bh1[1], bh1[3]);
                    mma_bf16(c[m][3], a0,a1,a2,a3, bl1[1], bl1[3]);
                }
            }
            #pragma unroll
            for (int nt = 0; nt < 4; ++nt) {
                int n0 = wn*32 + nt*8 + tig*2;
                float bb0 = s_b2[n0], bb1 = s_b2[n0+1];
                float p0 = 0.f, p1 = 0.f;
                #pragma unroll
                for (int m = 0; m < 2; ++m) {
                    p0 += fmaxf(c[m][nt][0]+bb0, 0.f) + fmaxf(c[m][nt][2]+bb0, 0.f);
                    p1 += fmaxf(c[m][nt][1]+bb1, 0.f) + fmaxf(c[m][nt][3]+bb1, 0.f);
                }
                #pragma unroll
                for (int off = 4; off < 32; off <<= 1) {
                    p0 += __shfl_xor_sync(0xffffffffu, p0, off);
                    p1 += __shfl_xor_sync(0xffffffffu, p1, off);
                }
                if (lane < 4) {
                    atomicAdd(&s_red[n0],   p0);
                    atomicAdd(&s_red[n0+1], p1);
                }
            }
        }
        __syncthreads();
        if (tid < 128) g_m[(size_t)tb*HD_ + tid] = s_red[tid] * (1.0f/(float)V_);
        __syncthreads();
    }
}

// ---------------- K4a: cumsum over t ------------------------------------------------------
__global__ void k4a_cumsum() {
    int gid = blockIdx.x * 1024 + threadIdx.x;
    int b = gid >> 7, h = gid & 127;
    float run = 0.f;
    for (int t = 0; t < T_; ++t) {
        size_t idx = ((size_t)t*B_ + b)*HD_ + h;
        run += g_m[idx];
        g_m[idx] = run;
    }
}

// ---------------- K4b: gi = cum @ Wih^T + bih ---------------------------------------------
__global__ __launch_bounds__(384) void k4b_gi(const float* __restrict__ Wih, const float* __restrict__ bih) {
    __shared__ float s_c[128];
    int tb = blockIdx.x, tid = threadIdx.x;
    if (tid < 128) s_c[tid] = g_m[(size_t)tb*HD_ + tid];
    __syncthreads();
    float a0 = bih[tid], a1 = 0.f, a2 = 0.f, a3 = 0.f;
    const float* wr = Wih + (size_t)tid*HD_;
    #pragma unroll 8
    for (int k = 0; k < HD_; k += 4) {
        a0 = fmaf(s_c[k  ], wr[k  ], a0);
        a1 = fmaf(s_c[k+1], wr[k+1], a1);
        a2 = fmaf(s_c[k+2], wr[k+2], a2);
        a3 = fmaf(s_c[k+3], wr[k+3], a3);
    }
    g_gi[(size_t)tb*3*HD_ + tid] = (a0+a1)+(a2+a3);
}

// ---------------- K5: GRU (batch 16 only) -------------------------------------------------
__global__ __launch_bounds__(384) void k5_gru(const float* __restrict__ Whh, const float* __restrict__ bhh) {
    extern __shared__ float sm[];
    float* s_W  = sm;
    float* s_h  = sm + 384*129;
    float* s_gh = s_h + 128;
    int b = blockIdx.x, tid = threadIdx.x;
    for (int idx = tid; idx < 384*HD_; idx += 384) {
        int g = idx >> 7, k = idx & 127;
        s_W[g*129 + k] = Whh[idx];
    }
    float bh = bhh[tid];
    if (tid < 128) s_h[tid] = 0.f;
    __syncthreads();
    const float* wr = s_W + tid*129;
    for (int t = 0; t < T_; ++t) {
        float a0 = bh, a1 = 0.f, a2 = 0.f, a3 = 0.f;
        #pragma unroll 8
        for (int k = 0; k < HD_; k += 4) {
            a0 = fmaf(s_h[k  ], wr[k  ], a0);
            a1 = fmaf(s_h[k+1], wr[k+1], a1);
            a2 = fmaf(s_h[k+2], wr[k+2], a2);
            a3 = fmaf(s_h[k+3], wr[k+3], a3);
        }
        s_gh[tid] = (a0+a1)+(a2+a3);
        __syncthreads();
        if (tid < 128) {
            size_t row = ((size_t)t*B_ + b)*3*HD_;
            float r  = 1.f/(1.f + expf(-(g_gi[row +        tid] + s_gh[tid])));
            float z  = 1.f/(1.f + expf(-(g_gi[row + HD_ +  tid] + s_gh[HD_ + tid])));
            float nn = tanhf(g_gi[row + 2*HD_ + tid] + r*s_gh[2*HD_ + tid]);
            float hp = s_h[tid];
            float hv = (1.f - z)*nn + z*hp;
            s_h[tid] = hv;
            g_y[((size_t)t*B_ + b)*HD_ + tid] = hv;
        }
        __syncthreads();
    }
}

// ---------------- K6: output projection + HN broadcast ------------------------------------
__global__ __launch_bounds__(256) void k6_out(const float* __restrict__ Wo, const float* __restrict__ bo,
                                              float* __restrict__ out) {
    __shared__ float s_y[128];
    __shared__ float s_o[64];
    int bt = blockIdx.x;
    int b = bt >> 5, t = bt & 31;
    int tid = threadIdx.x;
    if (tid < 128) s_y[tid] = g_y[((size_t)t*B_ + b)*HD_ + tid];
    __syncthreads();
    if (tid < DOUT_) {
        float a0 = bo[tid], a1 = 0.f, a2 = 0.f, a3 = 0.f;
        #pragma unroll 8
        for (int h = 0; h < HD_; h += 4) {
            a0 = fmaf(s_y[h  ], Wo[(h  )*DOUT_ + tid], a0);
            a1 = fmaf(s_y[h+1], Wo[(h+1)*DOUT_ + tid], a1);
            a2 = fmaf(s_y[h+2], Wo[(h+2)*DOUT_ + tid], a2);
            a3 = fmaf(s_y[h+3], Wo[(h+3)*DOUT_ + tid], a3);
        }
        s_o[tid] = (a0+a1)+(a2+a3);
    }
    __syncthreads();
    for (int idx = tid; idx < HN_*DOUT_; idx += 256) {
        int hn = idx >> 6, d = idx & 63;
        out[(((size_t)b*HN_ + hn)*T_ + t)*DOUT_ + d] = s_o[d];
    }
}

// ---------------- launch ------------------------------------------------------------------
extern "C" void kernel_launch(void* const* d_in, const int* in_sizes, int n_in,
                              void* d_out, int out_size) {
    const float* x   = (const float*)d_in[0];
    const float* adj = (const float*)d_in[1];
    const float* Wp  = (const float*)d_in[2];
    const float* bp  = (const float*)d_in[3];
    const float* W1  = (const float*)d_in[4];
    const float* b1  = (const float*)d_in[5];
    const float* W2  = (const float*)d_in[6];
    const float* b2  = (const float*)d_in[7];
    const float* Wn1 = (const float*)d_in[8];
    const float* bn1 = (const float*)d_in[9];
    const float* Wn2 = (const float*)d_in[10];
    const float* bn2 = (const float*)d_in[11];
    const float* Wih = (const float*)d_in[12];
    const float* Whh = (const float*)d_in[13];
    const float* bih = (const float*)d_in[14];
    const float* bhh = (const float*)d_in[15];
    const float* Wo  = (const float*)d_in[16];
    const float* bo  = (const float*)d_in[17];
    float* out = (float*)d_out;

    size_t smem1 = (size_t)(2*128*XS*2 + 2*256*XS*2 + 256*4);     // 111,616 B
    size_t smem2 = (size_t)K2_SMEM;                               // 74,304 B
    size_t smem3 = (size_t)(6 * 128 * WS * 2 + (128*3) * 4);      // 210,432 B
    size_t smem5 = (size_t)(384*129 + 128 + 384) * sizeof(float);

    cudaFuncSetAttribute(k1_mma,      cudaFuncAttributeMaxDynamicSharedMemorySize, (int)smem1);
    cudaFuncSetAttribute(k2_edge_mma, cudaFuncAttributeMaxDynamicSharedMemorySize, (int)smem2);
    cudaFuncSetAttribute(k3_node_mma, cudaFuncAttributeMaxDynamicSharedMemorySize, (int)smem3);
    cudaFuncSetAttribute(k5_gru,      cudaFuncAttributeMaxDynamicSharedMemorySize, (int)smem5);

    k0_prep    <<<DIN_ + 1, 256>>>(Wp, bp, W1, b1);
    k0c_w64    <<<64, 256>>>();
    k1b_compact<<<256, 256>>>(adj);
    k1_mma     <<<NTB, 256, smem1>>>(x);
    k2_edge_mma<<<K2GRID, 512, smem2>>>(W2, b2);
    k3_node_mma<<<K3GRID, 512, smem3>>>(Wn1, bn1, Wn2, bn2);
    k4a_cumsum <<<2, 1024>>>();
    k4b_gi     <<<NTB, 384>>>(Wih, bih);
    k5_gru     <<<B_, 384, smem5>>>(Whh, bhh);
    k6_out     <<<B_*T_, 256>>>(Wo, bo, out);
}